// round 11
// baseline (speedup 1.0000x reference)
#include <cuda_runtime.h>
#include <cuda_bf16.h>
#include <math.h>

// encoded: (8, 64, 256, 256) f32, masks: (8,1,256,256) i32 (0..32)
// W1: (128,32), b1: (32,), W2: (32,4), b2: (4,)
// out: vectors (8,32,64) ++ connections (8,4,32,32)

#define BATCH 8
#define FDIM 64
#define HW 65536
#define SEGS 33
#define NOBJ 32

__device__ unsigned char g_mask8[BATCH * HW];

// ---------------------------------------------------------------------------
// K0: pack int32 masks -> uint8.
// ---------------------------------------------------------------------------
__global__ __launch_bounds__(256) void pack_mask_kernel(const int* __restrict__ masks)
{
    int i = blockIdx.x * blockDim.x + threadIdx.x;
    int4 v = ((const int4*)masks)[i];
    unsigned int o = (v.x & 0xff) | ((v.y & 0xff) << 8) |
                     ((v.z & 0xff) << 16) | (v.w << 24);
    ((unsigned int*)g_mask8)[i] = o;
}

// ---------------------------------------------------------------------------
// K1: segment max. 256 blocks x 256 threads, 2 f-planes per block.
// Conflict-free float2 accumulators acc2[s*256 + t].
// NEW: predicated stores — running max over random data improves only
// O(log n) times, so ~97% of STS.64 (and their chain tails) vanish.
// ---------------------------------------------------------------------------
__global__ __launch_bounds__(256) void segmax_kernel(
    const float* __restrict__ enc, float* __restrict__ vec_out)
{
    extern __shared__ float2 acc2[];            // SEGS*256 float2 = 67584 B

    const int bf = blockIdx.x;                  // 0..255
    const int b  = bf >> 5;
    const int f0 = bf & 31;                     // planes f0, f0+32

    const int t = threadIdx.x;
    const float NEG_INF = __int_as_float(0xff800000);
#pragma unroll
    for (int s = 0; s < SEGS; s++) acc2[s * 256 + t] = make_float2(NEG_INF, NEG_INF);
    // each thread only touches its own column t -> no sync needed

    const float4* p0 = (const float4*)(enc + ((size_t)b * FDIM + f0) * HW);
    const float4* p1 = (const float4*)(enc + ((size_t)b * FDIM + f0 + 32) * HW);
    const uchar4* m4 = (const uchar4*)(g_mask8 + (size_t)b * HW);

    float2* ac = acc2 + t;

    // software-pipelined: next iteration's loads issue before this one's smem work
    int idx = t;
    float4 v0 = p0[idx];
    float4 v1 = p1[idx];
    uchar4 m  = m4[idx];

#pragma unroll 2
    for (int i = 0; i < 63; i++) {
        const int nidx = idx + 256;
        float4 nv0 = p0[nidx];
        float4 nv1 = p1[nidx];
        uchar4 nm  = m4[nidx];

        {
            float2* px = ac + (int)m.x * 256;
            float2 a = *px;
            if ((v0.x > a.x) | (v1.x > a.y)) {
                a.x = fmaxf(a.x, v0.x); a.y = fmaxf(a.y, v1.x); *px = a;
            }
        }
        {
            float2* py = ac + (int)m.y * 256;
            float2 a = *py;
            if ((v0.y > a.x) | (v1.y > a.y)) {
                a.x = fmaxf(a.x, v0.y); a.y = fmaxf(a.y, v1.y); *py = a;
            }
        }
        {
            float2* pz = ac + (int)m.z * 256;
            float2 a = *pz;
            if ((v0.z > a.x) | (v1.z > a.y)) {
                a.x = fmaxf(a.x, v0.z); a.y = fmaxf(a.y, v1.z); *pz = a;
            }
        }
        {
            float2* pw = ac + (int)m.w * 256;
            float2 a = *pw;
            if ((v0.w > a.x) | (v1.w > a.y)) {
                a.x = fmaxf(a.x, v0.w); a.y = fmaxf(a.y, v1.w); *pw = a;
            }
        }

        v0 = nv0; v1 = nv1; m = nm; idx = nidx;
    }
    // epilogue iteration
    {
        float2* px = ac + (int)m.x * 256;
        float2 a = *px;
        if ((v0.x > a.x) | (v1.x > a.y)) { a.x = fmaxf(a.x, v0.x); a.y = fmaxf(a.y, v1.x); *px = a; }
        float2* py = ac + (int)m.y * 256;
        a = *py;
        if ((v0.y > a.x) | (v1.y > a.y)) { a.x = fmaxf(a.x, v0.y); a.y = fmaxf(a.y, v1.y); *py = a; }
        float2* pz = ac + (int)m.z * 256;
        a = *pz;
        if ((v0.z > a.x) | (v1.z > a.y)) { a.x = fmaxf(a.x, v0.z); a.y = fmaxf(a.y, v1.z); *pz = a; }
        float2* pw = ac + (int)m.w * 256;
        a = *pw;
        if ((v0.w > a.x) | (v1.w > a.y)) { a.x = fmaxf(a.x, v0.w); a.y = fmaxf(a.y, v1.w); *pw = a; }
    }

    __syncthreads();

    // Column reduce: 8 threads/segment, lane-staggered -> conflict-free.
    {
        const int sidx = t >> 3;                // segment sidx+1
        const int k    = t & 7;
        const float2* base = acc2 + (sidx + 1) * 256 + k * 32;
        float mx = NEG_INF, my = NEG_INF;
#pragma unroll
        for (int i = 0; i < 32; i++) {
            int j = (i + t) & 31;
            float2 v = base[j];
            mx = fmaxf(mx, v.x);
            my = fmaxf(my, v.y);
        }
        mx = fmaxf(mx, __shfl_down_sync(0xffffffffu, mx, 4, 8));
        mx = fmaxf(mx, __shfl_down_sync(0xffffffffu, mx, 2, 8));
        mx = fmaxf(mx, __shfl_down_sync(0xffffffffu, mx, 1, 8));
        my = fmaxf(my, __shfl_down_sync(0xffffffffu, my, 4, 8));
        my = fmaxf(my, __shfl_down_sync(0xffffffffu, my, 2, 8));
        my = fmaxf(my, __shfl_down_sync(0xffffffffu, my, 1, 8));
        if (k == 0) {
            float* vrow = vec_out + ((size_t)b * NOBJ + sidx) * FDIM;
            vrow[f0]      = mx;
            vrow[f0 + 32] = my;
        }
    }
}

// ---------------------------------------------------------------------------
// K2: pair MLP — 32 blocks (8 batches x 4 i-tiles), 256 threads (R6, measured).
// ---------------------------------------------------------------------------
__global__ __launch_bounds__(256) void pair_mlp_kernel(
    const float* __restrict__ vec, const float* __restrict__ W1,
    const float* __restrict__ b1, const float* __restrict__ W2,
    const float* __restrict__ b2, float* __restrict__ conn)
{
    const int b    = blockIdx.x >> 2;
    const int tile = blockIdx.x & 3;        // i in [tile*8, tile*8+8)
    const int t    = threadIdx.x;

    __shared__ float sW1[128 * 32];
    __shared__ float sV[32][64];
    __shared__ float sA[8][SEGS];
    __shared__ float sB[32][SEGS];
    __shared__ float sW2[128];
    __shared__ float sb1[32];
    __shared__ float sb2[4];

    {
        const float4* w4 = (const float4*)W1;
#pragma unroll
        for (int r = 0; r < 4; r++) ((float4*)sW1)[r * 256 + t] = w4[r * 256 + t];
        const float4* v4 = (const float4*)(vec + (size_t)b * 2048);
#pragma unroll
        for (int r = 0; r < 2; r++) {
            int idx = r * 256 + t;
            ((float4*)sV)[idx] = v4[idx];
        }
        if (t < 128) sW2[t] = W2[t];
        if (t < 32)  sb1[t] = b1[t];
        if (t < 4)   sb2[t] = b2[t];
    }
    __syncthreads();

    {
        const int il = t >> 5;              // 0..7 (warp-uniform)
        const int k  = t & 31;              // lane
        const int i  = tile * 8 + il;
        float a = sb1[k];
#pragma unroll 8
        for (int d = 0; d < 64; d++)
            a += sV[i][d] * sW1[d * 32 + k];
        sA[il][k] = a;

#pragma unroll
        for (int r = 0; r < 4; r++) {
            const int j = r * 8 + il;
            float bb = 0.f;
#pragma unroll 8
            for (int d = 0; d < 64; d++)
                bb += sV[j][d] * sW1[(64 + d) * 32 + k];
            sB[j][k] = bb;
        }
    }
    __syncthreads();

    {
        const int il = t >> 5;
        const int j  = t & 31;
        const int i  = tile * 8 + il;
        float o0 = sb2[0], o1 = sb2[1], o2 = sb2[2], o3 = sb2[3];
#pragma unroll
        for (int k = 0; k < 32; k++) {
            float h = sA[il][k] + sB[j][k];
            o0 += h * sW2[k * 4 + 0];
            o1 += h * sW2[k * 4 + 1];
            o2 += h * sW2[k * 4 + 2];
            o3 += h * sW2[k * 4 + 3];
        }
        float* cb = conn + (size_t)b * 4096 + j * 32 + i;
        cb[0]    = 1.f / (1.f + __expf(-o0));
        cb[1024] = 1.f / (1.f + __expf(-o1));
        cb[2048] = 1.f / (1.f + __expf(-o2));
        cb[3072] = 1.f / (1.f + __expf(-o3));
    }
}

// ---------------------------------------------------------------------------
extern "C" void kernel_launch(void* const* d_in, const int* in_sizes, int n_in,
                              void* d_out, int out_size)
{
    const float* enc   = (const float*)d_in[0];
    const int*   masks = (const int*)  d_in[1];
    const float* W1    = (const float*)d_in[2];
    const float* b1    = (const float*)d_in[3];
    const float* W2    = (const float*)d_in[4];
    const float* b2    = (const float*)d_in[5];

    float* out_f = (float*)d_out;
    float* vectors = out_f;
    float* conn    = out_f + BATCH * NOBJ * FDIM;

    static bool attr_done = false;
    if (!attr_done) {
        cudaFuncSetAttribute(segmax_kernel,
                             cudaFuncAttributeMaxDynamicSharedMemorySize,
                             SEGS * 256 * (int)sizeof(float2));
        attr_done = true;
    }

    pack_mask_kernel<<<512, 256>>>(masks);
    segmax_kernel<<<BATCH * 32, 256, SEGS * 256 * sizeof(float2)>>>(enc, vectors);
    pair_mlp_kernel<<<BATCH * 4, 256>>>(vectors, W1, b1, W2, b2, conn);
}

// round 12
// speedup vs baseline: 1.0457x; 1.0457x over previous
#include <cuda_runtime.h>
#include <cuda_bf16.h>
#include <math.h>

// encoded: (8, 64, 256, 256) f32, masks: (8,1,256,256) i32 (0..32)
// W1: (128,32), b1: (32,), W2: (32,4), b2: (4,)
// out: vectors (8,32,64) ++ connections (8,4,32,32)

#define BATCH 8
#define FDIM 64
#define HW 65536
#define SEGS 33
#define NOBJ 32

__device__ unsigned char g_mask8[BATCH * HW];

// ---------------------------------------------------------------------------
// K0: pack int32 masks -> uint8.
// ---------------------------------------------------------------------------
__global__ __launch_bounds__(256) void pack_mask_kernel(const int* __restrict__ masks)
{
    int i = blockIdx.x * blockDim.x + threadIdx.x;
    int4 v = ((const int4*)masks)[i];
    unsigned int o = (v.x & 0xff) | ((v.y & 0xff) << 8) |
                     ((v.z & 0xff) << 16) | (v.w << 24);
    ((unsigned int*)g_mask8)[i] = o;
}

// ---------------------------------------------------------------------------
// K1: segment max — 128 blocks x 512 threads, 1 block/SM (135KB smem),
// perfectly balanced across SMs, 16 warps/SM for latency hiding.
// Each block processes TWO plane-pairs sequentially (4 planes total):
// pass p handles planes (2q+p, 2q+p+32), q = blockIdx%16, b = blockIdx/16.
// Conflict-free float2 accumulators acc2[s*512 + t] (stride is bank-aligned).
// ---------------------------------------------------------------------------
__global__ __launch_bounds__(512) void segmax_kernel(
    const float* __restrict__ enc, float* __restrict__ vec_out)
{
    extern __shared__ float2 acc2[];            // SEGS*512 float2 = 135168 B

    const int blk = blockIdx.x;                 // 0..127
    const int b   = blk >> 4;                   // 0..7
    const int q   = blk & 15;                   // 0..15

    const int t = threadIdx.x;                  // 0..511
    const float NEG_INF = __int_as_float(0xff800000);

    const uchar4* m4base = (const uchar4*)(g_mask8 + (size_t)b * HW);

#pragma unroll
    for (int pass = 0; pass < 2; pass++) {
        const int f0 = q * 2 + pass;            // planes f0, f0+32

        // init own column (no sync needed: each thread touches only column t)
#pragma unroll
        for (int s = 0; s < SEGS; s++) acc2[s * 512 + t] = make_float2(NEG_INF, NEG_INF);

        const float4* p0 = (const float4*)(enc + ((size_t)b * FDIM + f0) * HW);
        const float4* p1 = (const float4*)(enc + ((size_t)b * FDIM + f0 + 32) * HW);

        float2* ac = acc2 + t;

        // 65536 pixels / (512 threads * 4-wide) = 32 iterations
#pragma unroll 4
        for (int i = 0; i < 32; i++) {
            int idx = i * 512 + t;
            float4 v0 = p0[idx];
            float4 v1 = p1[idx];
            uchar4 m  = m4base[idx];
            float2* px = ac + (int)m.x * 512;
            float2* py = ac + (int)m.y * 512;
            float2* pz = ac + (int)m.z * 512;
            float2* pw = ac + (int)m.w * 512;
            float2 a0 = *px; a0.x = fmaxf(a0.x, v0.x); a0.y = fmaxf(a0.y, v1.x); *px = a0;
            float2 a1 = *py; a1.x = fmaxf(a1.x, v0.y); a1.y = fmaxf(a1.y, v1.y); *py = a1;
            float2 a2 = *pz; a2.x = fmaxf(a2.x, v0.z); a2.y = fmaxf(a2.y, v1.z); *pz = a2;
            float2 a3 = *pw; a3.x = fmaxf(a3.x, v0.w); a3.y = fmaxf(a3.y, v1.w); *pw = a3;
        }

        __syncthreads();

        // Reduce 512 columns/segment: 16 threads per segment, lane-staggered.
        {
            const int sidx = t >> 4;            // 0..31 -> segment sidx+1
            const int k    = t & 15;
            const float2* base = acc2 + (sidx + 1) * 512 + k * 32;
            float mx = NEG_INF, my = NEG_INF;
#pragma unroll
            for (int i = 0; i < 32; i++) {
                int j = (i + t) & 31;           // bank distinct per lane
                float2 v = base[j];
                mx = fmaxf(mx, v.x);
                my = fmaxf(my, v.y);
            }
            mx = fmaxf(mx, __shfl_down_sync(0xffffffffu, mx, 8, 16));
            mx = fmaxf(mx, __shfl_down_sync(0xffffffffu, mx, 4, 16));
            mx = fmaxf(mx, __shfl_down_sync(0xffffffffu, mx, 2, 16));
            mx = fmaxf(mx, __shfl_down_sync(0xffffffffu, mx, 1, 16));
            my = fmaxf(my, __shfl_down_sync(0xffffffffu, my, 8, 16));
            my = fmaxf(my, __shfl_down_sync(0xffffffffu, my, 4, 16));
            my = fmaxf(my, __shfl_down_sync(0xffffffffu, my, 2, 16));
            my = fmaxf(my, __shfl_down_sync(0xffffffffu, my, 1, 16));
            if (k == 0) {
                float* vrow = vec_out + ((size_t)b * NOBJ + sidx) * FDIM;
                vrow[f0]      = mx;
                vrow[f0 + 32] = my;
            }
        }

        __syncthreads();    // reduce reads all columns; protect pass-2 re-init
    }
}

// ---------------------------------------------------------------------------
// K2: pair MLP — 32 blocks (8 batches x 4 i-tiles), 256 threads (R6, measured).
// ---------------------------------------------------------------------------
__global__ __launch_bounds__(256) void pair_mlp_kernel(
    const float* __restrict__ vec, const float* __restrict__ W1,
    const float* __restrict__ b1, const float* __restrict__ W2,
    const float* __restrict__ b2, float* __restrict__ conn)
{
    const int b    = blockIdx.x >> 2;
    const int tile = blockIdx.x & 3;        // i in [tile*8, tile*8+8)
    const int t    = threadIdx.x;

    __shared__ float sW1[128 * 32];
    __shared__ float sV[32][64];
    __shared__ float sA[8][SEGS];
    __shared__ float sB[32][SEGS];
    __shared__ float sW2[128];
    __shared__ float sb1[32];
    __shared__ float sb2[4];

    {
        const float4* w4 = (const float4*)W1;
#pragma unroll
        for (int r = 0; r < 4; r++) ((float4*)sW1)[r * 256 + t] = w4[r * 256 + t];
        const float4* v4 = (const float4*)(vec + (size_t)b * 2048);
#pragma unroll
        for (int r = 0; r < 2; r++) {
            int idx = r * 256 + t;
            ((float4*)sV)[idx] = v4[idx];
        }
        if (t < 128) sW2[t] = W2[t];
        if (t < 32)  sb1[t] = b1[t];
        if (t < 4)   sb2[t] = b2[t];
    }
    __syncthreads();

    {
        const int il = t >> 5;              // 0..7 (warp-uniform)
        const int k  = t & 31;              // lane
        const int i  = tile * 8 + il;
        float a = sb1[k];
#pragma unroll 8
        for (int d = 0; d < 64; d++)
            a += sV[i][d] * sW1[d * 32 + k];
        sA[il][k] = a;

#pragma unroll
        for (int r = 0; r < 4; r++) {
            const int j = r * 8 + il;
            float bb = 0.f;
#pragma unroll 8
            for (int d = 0; d < 64; d++)
                bb += sV[j][d] * sW1[(64 + d) * 32 + k];
            sB[j][k] = bb;
        }
    }
    __syncthreads();

    {
        const int il = t >> 5;
        const int j  = t & 31;
        const int i  = tile * 8 + il;
        float o0 = sb2[0], o1 = sb2[1], o2 = sb2[2], o3 = sb2[3];
#pragma unroll
        for (int k = 0; k < 32; k++) {
            float h = sA[il][k] + sB[j][k];
            o0 += h * sW2[k * 4 + 0];
            o1 += h * sW2[k * 4 + 1];
            o2 += h * sW2[k * 4 + 2];
            o3 += h * sW2[k * 4 + 3];
        }
        float* cb = conn + (size_t)b * 4096 + j * 32 + i;
        cb[0]    = 1.f / (1.f + __expf(-o0));
        cb[1024] = 1.f / (1.f + __expf(-o1));
        cb[2048] = 1.f / (1.f + __expf(-o2));
        cb[3072] = 1.f / (1.f + __expf(-o3));
    }
}

// ---------------------------------------------------------------------------
extern "C" void kernel_launch(void* const* d_in, const int* in_sizes, int n_in,
                              void* d_out, int out_size)
{
    const float* enc   = (const float*)d_in[0];
    const int*   masks = (const int*)  d_in[1];
    const float* W1    = (const float*)d_in[2];
    const float* b1    = (const float*)d_in[3];
    const float* W2    = (const float*)d_in[4];
    const float* b2    = (const float*)d_in[5];

    float* out_f = (float*)d_out;
    float* vectors = out_f;
    float* conn    = out_f + BATCH * NOBJ * FDIM;

    static bool attr_done = false;
    if (!attr_done) {
        cudaFuncSetAttribute(segmax_kernel,
                             cudaFuncAttributeMaxDynamicSharedMemorySize,
                             SEGS * 512 * (int)sizeof(float2));
        attr_done = true;
    }

    pack_mask_kernel<<<512, 256>>>(masks);
    segmax_kernel<<<128, 512, SEGS * 512 * sizeof(float2)>>>(enc, vectors);
    pair_mlp_kernel<<<BATCH * 4, 256>>>(vectors, W1, b1, W2, b2, conn);
}

// round 14
// speedup vs baseline: 1.0849x; 1.0374x over previous
#include <cuda_runtime.h>
#include <cuda_bf16.h>
#include <math.h>

// encoded: (8, 64, 256, 256) f32, masks: (8,1,256,256) i32 (0..32)
// W1: (128,32), b1: (32,), W2: (32,4), b2: (4,)
// out: vectors (8,32,64) ++ connections (8,4,32,32)

#define BATCH 8
#define FDIM 64
#define HW 65536
#define SEGS 33
#define NOBJ 32

__device__ unsigned char g_mask8[BATCH * HW];
__device__ float g_sink;

// ---------------------------------------------------------------------------
// K0: pack int32 masks -> uint8; also warm W1/W2 into L2 for the MLP.
// ---------------------------------------------------------------------------
__global__ __launch_bounds__(256) void pack_mask_kernel(
    const int* __restrict__ masks, const float* __restrict__ W1,
    const float* __restrict__ W2)
{
    int i = blockIdx.x * blockDim.x + threadIdx.x;
    int4 v = ((const int4*)masks)[i];
    unsigned int o = (v.x & 0xff) | ((v.y & 0xff) << 8) |
                     ((v.z & 0xff) << 16) | (v.w << 24);
    ((unsigned int*)g_mask8)[i] = o;

    if (blockIdx.x == 0) {
        // touch all 4096 W1 floats + 128 W2 floats (16.5 KB) into L2
        float w = W1[threadIdx.x * 16] + W1[threadIdx.x * 16 + 8] + W2[threadIdx.x & 127];
        if (w == 1234.56789f) g_sink = w;   // never true; keeps loads alive
    }
}

// ---------------------------------------------------------------------------
// K1: segment max (R6 core — measured best shape).
// 256 blocks x 256 threads, 2 f-planes per block, packed uchar4 masks,
// conflict-free float2 accumulators acc2[s*256 + t].
// NEW: __ldcs on enc (streaming, evict-first) — enc has zero reuse and
// otherwise flushes the packed masks out of L2 every invocation.
// ---------------------------------------------------------------------------
__global__ __launch_bounds__(256) void segmax_kernel(
    const float* __restrict__ enc, float* __restrict__ vec_out)
{
    extern __shared__ float2 acc2[];            // SEGS*256 float2 = 67584 B

    const int bf = blockIdx.x;                  // 0..255
    const int b  = bf >> 5;
    const int f0 = bf & 31;                     // planes f0, f0+32

    const int t = threadIdx.x;
    const float NEG_INF = __int_as_float(0xff800000);
#pragma unroll
    for (int s = 0; s < SEGS; s++) acc2[s * 256 + t] = make_float2(NEG_INF, NEG_INF);
    // each thread only touches its own column t -> no sync needed

    const float4* p0 = (const float4*)(enc + ((size_t)b * FDIM + f0) * HW);
    const float4* p1 = (const float4*)(enc + ((size_t)b * FDIM + f0 + 32) * HW);
    const uchar4* m4 = (const uchar4*)(g_mask8 + (size_t)b * HW);

    float2* ac = acc2 + t;

#pragma unroll 4
    for (int i = 0; i < 64; i++) {
        int idx = i * 256 + t;                  // coalesced
        float4 v0 = __ldcs(p0 + idx);           // streaming: evict-first
        float4 v1 = __ldcs(p1 + idx);
        uchar4 m  = m4[idx];                    // normal: keep in L2
        float2* px = ac + (int)m.x * 256;
        float2* py = ac + (int)m.y * 256;
        float2* pz = ac + (int)m.z * 256;
        float2* pw = ac + (int)m.w * 256;
        float2 a0 = *px; a0.x = fmaxf(a0.x, v0.x); a0.y = fmaxf(a0.y, v1.x); *px = a0;
        float2 a1 = *py; a1.x = fmaxf(a1.x, v0.y); a1.y = fmaxf(a1.y, v1.y); *py = a1;
        float2 a2 = *pz; a2.x = fmaxf(a2.x, v0.z); a2.y = fmaxf(a2.y, v1.z); *pz = a2;
        float2 a3 = *pw; a3.x = fmaxf(a3.x, v0.w); a3.y = fmaxf(a3.y, v1.w); *pw = a3;
    }

    __syncthreads();

    // Column reduce: 8 threads/segment, lane-staggered -> conflict-free.
    {
        const int sidx = t >> 3;                // segment sidx+1
        const int k    = t & 7;
        const float2* base = acc2 + (sidx + 1) * 256 + k * 32;
        float mx = NEG_INF, my = NEG_INF;
#pragma unroll
        for (int i = 0; i < 32; i++) {
            int j = (i + t) & 31;
            float2 v = base[j];
            mx = fmaxf(mx, v.x);
            my = fmaxf(my, v.y);
        }
        mx = fmaxf(mx, __shfl_down_sync(0xffffffffu, mx, 4, 8));
        mx = fmaxf(mx, __shfl_down_sync(0xffffffffu, mx, 2, 8));
        mx = fmaxf(mx, __shfl_down_sync(0xffffffffu, mx, 1, 8));
        my = fmaxf(my, __shfl_down_sync(0xffffffffu, my, 4, 8));
        my = fmaxf(my, __shfl_down_sync(0xffffffffu, my, 2, 8));
        my = fmaxf(my, __shfl_down_sync(0xffffffffu, my, 1, 8));
        if (k == 0) {
            float* vrow = vec_out + ((size_t)b * NOBJ + sidx) * FDIM;
            vrow[f0]      = mx;
            vrow[f0 + 32] = my;
        }
    }
}

// ---------------------------------------------------------------------------
// K2: pair MLP — 32 blocks (8 batches x 4 i-tiles), 256 threads (R6, measured).
// ---------------------------------------------------------------------------
__global__ __launch_bounds__(256) void pair_mlp_kernel(
    const float* __restrict__ vec, const float* __restrict__ W1,
    const float* __restrict__ b1, const float* __restrict__ W2,
    const float* __restrict__ b2, float* __restrict__ conn)
{
    const int b    = blockIdx.x >> 2;
    const int tile = blockIdx.x & 3;        // i in [tile*8, tile*8+8)
    const int t    = threadIdx.x;

    __shared__ float sW1[128 * 32];
    __shared__ float sV[32][64];
    __shared__ float sA[8][SEGS];
    __shared__ float sB[32][SEGS];
    __shared__ float sW2[128];
    __shared__ float sb1[32];
    __shared__ float sb2[4];

    {
        const float4* w4 = (const float4*)W1;
#pragma unroll
        for (int r = 0; r < 4; r++) ((float4*)sW1)[r * 256 + t] = w4[r * 256 + t];
        const float4* v4 = (const float4*)(vec + (size_t)b * 2048);
#pragma unroll
        for (int r = 0; r < 2; r++) {
            int idx = r * 256 + t;
            ((float4*)sV)[idx] = v4[idx];
        }
        if (t < 128) sW2[t] = W2[t];
        if (t < 32)  sb1[t] = b1[t];
        if (t < 4)   sb2[t] = b2[t];
    }
    __syncthreads();

    {
        const int il = t >> 5;              // 0..7 (warp-uniform)
        const int k  = t & 31;              // lane
        const int i  = tile * 8 + il;
        float a = sb1[k];
#pragma unroll 8
        for (int d = 0; d < 64; d++)
            a += sV[i][d] * sW1[d * 32 + k];
        sA[il][k] = a;

#pragma unroll
        for (int r = 0; r < 4; r++) {
            const int j = r * 8 + il;
            float bb = 0.f;
#pragma unroll 8
            for (int d = 0; d < 64; d++)
                bb += sV[j][d] * sW1[(64 + d) * 32 + k];
            sB[j][k] = bb;
        }
    }
    __syncthreads();

    {
        const int il = t >> 5;
        const int j  = t & 31;
        const int i  = tile * 8 + il;
        float o0 = sb2[0], o1 = sb2[1], o2 = sb2[2], o3 = sb2[3];
#pragma unroll
        for (int k = 0; k < 32; k++) {
            float h = sA[il][k] + sB[j][k];
            o0 += h * sW2[k * 4 + 0];
            o1 += h * sW2[k * 4 + 1];
            o2 += h * sW2[k * 4 + 2];
            o3 += h * sW2[k * 4 + 3];
        }
        float* cb = conn + (size_t)b * 4096 + j * 32 + i;
        cb[0]    = 1.f / (1.f + __expf(-o0));
        cb[1024] = 1.f / (1.f + __expf(-o1));
        cb[2048] = 1.f / (1.f + __expf(-o2));
        cb[3072] = 1.f / (1.f + __expf(-o3));
    }
}

// ---------------------------------------------------------------------------
extern "C" void kernel_launch(void* const* d_in, const int* in_sizes, int n_in,
                              void* d_out, int out_size)
{
    const float* enc   = (const float*)d_in[0];
    const int*   masks = (const int*)  d_in[1];
    const float* W1    = (const float*)d_in[2];
    const float* b1    = (const float*)d_in[3];
    const float* W2    = (const float*)d_in[4];
    const float* b2    = (const float*)d_in[5];

    float* out_f = (float*)d_out;
    float* vectors = out_f;
    float* conn    = out_f + BATCH * NOBJ * FDIM;

    static bool attr_done = false;
    if (!attr_done) {
        cudaFuncSetAttribute(segmax_kernel,
                             cudaFuncAttributeMaxDynamicSharedMemorySize,
                             SEGS * 256 * (int)sizeof(float2));
        attr_done = true;
    }

    pack_mask_kernel<<<512, 256>>>(masks, W1, W2);
    segmax_kernel<<<BATCH * 32, 256, SEGS * 256 * sizeof(float2)>>>(enc, vectors);
    pair_mlp_kernel<<<BATCH * 4, 256>>>(vectors, W1, b1, W2, b2, conn);
}

// round 16
// speedup vs baseline: 1.1397x; 1.0506x over previous
#include <cuda_runtime.h>
#include <cuda_bf16.h>
#include <math.h>

// encoded: (8, 64, 256, 256) f32, masks: (8,1,256,256) i32 (0..32)
// W1: (128,32), b1: (32,), W2: (32,4), b2: (4,)
// out: vectors (8,32,64) ++ connections (8,4,32,32)

#define BATCH 8
#define FDIM 64
#define HW 65536
#define SEGS 33
#define NOBJ 32

#define SEG_BLOCKS 256
#define PACK_PER_BATCH 4
#define PACK_BLOCKS (BATCH * PACK_PER_BATCH)   // 32

__device__ unsigned char g_mask8[BATCH * HW];
__device__ int g_ready[BATCH];                 // reset by pair_mlp_kernel

// ---------------------------------------------------------------------------
// K1: combined launch — blocks [0,256): segment-max consumers;
//     blocks [256,288): mask-pack producers (4 per batch).
// All 288 blocks are simultaneously resident (67.5KB smem -> 3 blocks/SM ->
// 444 slots >= 288), so the spin-wait cannot deadlock.
// ---------------------------------------------------------------------------
__global__ __launch_bounds__(256) void segmax_kernel(
    const float* __restrict__ enc, const int* __restrict__ masks,
    float* __restrict__ vec_out)
{
    extern __shared__ float2 acc2[];            // SEGS*256 float2 = 67584 B
    const int t = threadIdx.x;

    // ---------------- producer role: pack masks ----------------
    if (blockIdx.x >= SEG_BLOCKS) {
        const int p = blockIdx.x - SEG_BLOCKS;  // 0..31
        const int b = p >> 2;
        const int quarter = p & 3;
        const int4* in4 = (const int4*)(masks + (size_t)b * HW) + quarter * 4096;
        unsigned int* out1 = (unsigned int*)(g_mask8 + (size_t)b * HW) + quarter * 4096;
#pragma unroll
        for (int r = 0; r < 16; r++) {
            int idx = r * 256 + t;              // 4096 int4 per quarter
            int4 v = in4[idx];
            out1[idx] = (v.x & 0xff) | ((v.y & 0xff) << 8) |
                        ((v.z & 0xff) << 16) | (v.w << 24);
        }
        __threadfence();
        __syncthreads();
        if (t == 0) atomicAdd(&g_ready[b], 1);
        return;
    }

    // ---------------- consumer role: segment max (R6 core) ----------------
    const int bf = blockIdx.x;                  // 0..255
    const int b  = bf >> 5;
    const int f0 = bf & 31;                     // planes f0, f0+32

    const float NEG_INF = __int_as_float(0xff800000);
#pragma unroll
    for (int s = 0; s < SEGS; s++) acc2[s * 256 + t] = make_float2(NEG_INF, NEG_INF);

    // wait for this batch's 4 pack producers (init above overlaps the wait)
    if (t == 0) {
        while (atomicAdd(&g_ready[b], 0) < PACK_PER_BATCH) {
            __nanosleep(64);
        }
    }
    __syncthreads();
    __threadfence();                            // order subsequent reads

    const float4* p0 = (const float4*)(enc + ((size_t)b * FDIM + f0) * HW);
    const float4* p1 = (const float4*)(enc + ((size_t)b * FDIM + f0 + 32) * HW);
    const uchar4* m4 = (const uchar4*)(g_mask8 + (size_t)b * HW);

    float2* ac = acc2 + t;

#pragma unroll 4
    for (int i = 0; i < 64; i++) {
        int idx = i * 256 + t;                  // coalesced
        float4 v0 = p0[idx];
        float4 v1 = p1[idx];
        uchar4 m  = __ldcg(m4 + idx);           // L2-scope read of produced data
        float2* px = ac + (int)m.x * 256;
        float2* py = ac + (int)m.y * 256;
        float2* pz = ac + (int)m.z * 256;
        float2* pw = ac + (int)m.w * 256;
        float2 a0 = *px; a0.x = fmaxf(a0.x, v0.x); a0.y = fmaxf(a0.y, v1.x); *px = a0;
        float2 a1 = *py; a1.x = fmaxf(a1.x, v0.y); a1.y = fmaxf(a1.y, v1.y); *py = a1;
        float2 a2 = *pz; a2.x = fmaxf(a2.x, v0.z); a2.y = fmaxf(a2.y, v1.z); *pz = a2;
        float2 a3 = *pw; a3.x = fmaxf(a3.x, v0.w); a3.y = fmaxf(a3.y, v1.w); *pw = a3;
    }

    __syncthreads();

    // Column reduce: 8 threads/segment, lane-staggered -> conflict-free.
    {
        const int sidx = t >> 3;                // segment sidx+1
        const int k    = t & 7;
        const float2* base = acc2 + (sidx + 1) * 256 + k * 32;
        float mx = NEG_INF, my = NEG_INF;
#pragma unroll
        for (int i = 0; i < 32; i++) {
            int j = (i + t) & 31;
            float2 v = base[j];
            mx = fmaxf(mx, v.x);
            my = fmaxf(my, v.y);
        }
        mx = fmaxf(mx, __shfl_down_sync(0xffffffffu, mx, 4, 8));
        mx = fmaxf(mx, __shfl_down_sync(0xffffffffu, mx, 2, 8));
        mx = fmaxf(mx, __shfl_down_sync(0xffffffffu, mx, 1, 8));
        my = fmaxf(my, __shfl_down_sync(0xffffffffu, my, 4, 8));
        my = fmaxf(my, __shfl_down_sync(0xffffffffu, my, 2, 8));
        my = fmaxf(my, __shfl_down_sync(0xffffffffu, my, 1, 8));
        if (k == 0) {
            float* vrow = vec_out + ((size_t)b * NOBJ + sidx) * FDIM;
            vrow[f0]      = mx;
            vrow[f0 + 32] = my;
        }
    }
}

// ---------------------------------------------------------------------------
// K2: pair MLP — 32 blocks (8 batches x 4 i-tiles), 256 threads (R6, measured).
// Also resets g_ready for the next graph replay (runs strictly after segmax).
// ---------------------------------------------------------------------------
__global__ __launch_bounds__(256) void pair_mlp_kernel(
    const float* __restrict__ vec, const float* __restrict__ W1,
    const float* __restrict__ b1, const float* __restrict__ W2,
    const float* __restrict__ b2, float* __restrict__ conn)
{
    const int b    = blockIdx.x >> 2;
    const int tile = blockIdx.x & 3;        // i in [tile*8, tile*8+8)
    const int t    = threadIdx.x;

    if (tile == 0 && t == 0) atomicExch(&g_ready[b], 0);   // reset for next replay

    __shared__ float sW1[128 * 32];
    __shared__ float sV[32][64];
    __shared__ float sA[8][SEGS];
    __shared__ float sB[32][SEGS];
    __shared__ float sW2[128];
    __shared__ float sb1[32];
    __shared__ float sb2[4];

    {
        const float4* w4 = (const float4*)W1;
#pragma unroll
        for (int r = 0; r < 4; r++) ((float4*)sW1)[r * 256 + t] = w4[r * 256 + t];
        const float4* v4 = (const float4*)(vec + (size_t)b * 2048);
#pragma unroll
        for (int r = 0; r < 2; r++) {
            int idx = r * 256 + t;
            ((float4*)sV)[idx] = v4[idx];
        }
        if (t < 128) sW2[t] = W2[t];
        if (t < 32)  sb1[t] = b1[t];
        if (t < 4)   sb2[t] = b2[t];
    }
    __syncthreads();

    {
        const int il = t >> 5;              // 0..7 (warp-uniform)
        const int k  = t & 31;              // lane
        const int i  = tile * 8 + il;
        float a = sb1[k];
#pragma unroll 8
        for (int d = 0; d < 64; d++)
            a += sV[i][d] * sW1[d * 32 + k];
        sA[il][k] = a;

#pragma unroll
        for (int r = 0; r < 4; r++) {
            const int j = r * 8 + il;
            float bb = 0.f;
#pragma unroll 8
            for (int d = 0; d < 64; d++)
                bb += sV[j][d] * sW1[(64 + d) * 32 + k];
            sB[j][k] = bb;
        }
    }
    __syncthreads();

    {
        const int il = t >> 5;
        const int j  = t & 31;
        const int i  = tile * 8 + il;
        float o0 = sb2[0], o1 = sb2[1], o2 = sb2[2], o3 = sb2[3];
#pragma unroll
        for (int k = 0; k < 32; k++) {
            float h = sA[il][k] + sB[j][k];
            o0 += h * sW2[k * 4 + 0];
            o1 += h * sW2[k * 4 + 1];
            o2 += h * sW2[k * 4 + 2];
            o3 += h * sW2[k * 4 + 3];
        }
        float* cb = conn + (size_t)b * 4096 + j * 32 + i;
        cb[0]    = 1.f / (1.f + __expf(-o0));
        cb[1024] = 1.f / (1.f + __expf(-o1));
        cb[2048] = 1.f / (1.f + __expf(-o2));
        cb[3072] = 1.f / (1.f + __expf(-o3));
    }
}

// ---------------------------------------------------------------------------
extern "C" void kernel_launch(void* const* d_in, const int* in_sizes, int n_in,
                              void* d_out, int out_size)
{
    const float* enc   = (const float*)d_in[0];
    const int*   masks = (const int*)  d_in[1];
    const float* W1    = (const float*)d_in[2];
    const float* b1    = (const float*)d_in[3];
    const float* W2    = (const float*)d_in[4];
    const float* b2    = (const float*)d_in[5];

    float* out_f = (float*)d_out;
    float* vectors = out_f;
    float* conn    = out_f + BATCH * NOBJ * FDIM;

    static bool attr_done = false;
    if (!attr_done) {
        cudaFuncSetAttribute(segmax_kernel,
                             cudaFuncAttributeMaxDynamicSharedMemorySize,
                             SEGS * 256 * (int)sizeof(float2));
        attr_done = true;
    }

    segmax_kernel<<<SEG_BLOCKS + PACK_BLOCKS, 256, SEGS * 256 * sizeof(float2)>>>(
        enc, masks, vectors);
    pair_mlp_kernel<<<BATCH * 4, 256>>>(vectors, W1, b1, W2, b2, conn);
}

// round 17
// speedup vs baseline: 1.2342x; 1.0829x over previous
#include <cuda_runtime.h>
#include <cuda_bf16.h>
#include <math.h>

// encoded: (8, 64, 256, 256) f32, masks: (8,1,256,256) i32 (0..32)
// W1: (128,32), b1: (32,), W2: (32,4), b2: (4,)
// out: vectors (8,32,64) ++ connections (8,4,32,32)

#define BATCH 8
#define FDIM 64
#define HW 65536
#define SEGS 33
#define NOBJ 32

__device__ unsigned char g_mask8[BATCH * HW];

// ---------------------------------------------------------------------------
// K0: pack int32 masks -> uint8 (R6, measured).
// ---------------------------------------------------------------------------
__global__ __launch_bounds__(256) void pack_mask_kernel(const int* __restrict__ masks)
{
    int i = blockIdx.x * blockDim.x + threadIdx.x;
    int4 v = ((const int4*)masks)[i];
    unsigned int o = (v.x & 0xff) | ((v.y & 0xff) << 8) |
                     ((v.z & 0xff) << 16) | (v.w << 24);
    ((unsigned int*)g_mask8)[i] = o;
}

// ---------------------------------------------------------------------------
// K1: segment max (R6 core — measured best: ~29.5us).
// 256 blocks x 256 threads, 2 f-planes per block, packed uchar4 masks,
// conflict-free float2 accumulators acc2[s*256 + t].
// ---------------------------------------------------------------------------
__global__ __launch_bounds__(256) void segmax_kernel(
    const float* __restrict__ enc, float* __restrict__ vec_out)
{
    extern __shared__ float2 acc2[];            // SEGS*256 float2 = 67584 B

    const int bf = blockIdx.x;                  // 0..255
    const int b  = bf >> 5;
    const int f0 = bf & 31;                     // planes f0, f0+32

    const int t = threadIdx.x;
    const float NEG_INF = __int_as_float(0xff800000);
#pragma unroll
    for (int s = 0; s < SEGS; s++) acc2[s * 256 + t] = make_float2(NEG_INF, NEG_INF);

    const float4* p0 = (const float4*)(enc + ((size_t)b * FDIM + f0) * HW);
    const float4* p1 = (const float4*)(enc + ((size_t)b * FDIM + f0 + 32) * HW);
    const uchar4* m4 = (const uchar4*)(g_mask8 + (size_t)b * HW);

    float2* ac = acc2 + t;

#pragma unroll 4
    for (int i = 0; i < 64; i++) {
        int idx = i * 256 + t;
        float4 v0 = p0[idx];
        float4 v1 = p1[idx];
        uchar4 m  = m4[idx];
        float2* px = ac + (int)m.x * 256;
        float2* py = ac + (int)m.y * 256;
        float2* pz = ac + (int)m.z * 256;
        float2* pw = ac + (int)m.w * 256;
        float2 a0 = *px; a0.x = fmaxf(a0.x, v0.x); a0.y = fmaxf(a0.y, v1.x); *px = a0;
        float2 a1 = *py; a1.x = fmaxf(a1.x, v0.y); a1.y = fmaxf(a1.y, v1.y); *py = a1;
        float2 a2 = *pz; a2.x = fmaxf(a2.x, v0.z); a2.y = fmaxf(a2.y, v1.z); *pz = a2;
        float2 a3 = *pw; a3.x = fmaxf(a3.x, v0.w); a3.y = fmaxf(a3.y, v1.w); *pw = a3;
    }

    __syncthreads();

    {
        const int sidx = t >> 3;                // segment sidx+1
        const int k    = t & 7;
        const float2* base = acc2 + (sidx + 1) * 256 + k * 32;
        float mx = NEG_INF, my = NEG_INF;
#pragma unroll
        for (int i = 0; i < 32; i++) {
            int j = (i + t) & 31;
            float2 v = base[j];
            mx = fmaxf(mx, v.x);
            my = fmaxf(my, v.y);
        }
        mx = fmaxf(mx, __shfl_down_sync(0xffffffffu, mx, 4, 8));
        mx = fmaxf(mx, __shfl_down_sync(0xffffffffu, mx, 2, 8));
        mx = fmaxf(mx, __shfl_down_sync(0xffffffffu, mx, 1, 8));
        my = fmaxf(my, __shfl_down_sync(0xffffffffu, my, 4, 8));
        my = fmaxf(my, __shfl_down_sync(0xffffffffu, my, 2, 8));
        my = fmaxf(my, __shfl_down_sync(0xffffffffu, my, 1, 8));
        if (k == 0) {
            float* vrow = vec_out + ((size_t)b * NOBJ + sidx) * FDIM;
            vrow[f0]      = mx;
            vrow[f0 + 32] = my;
        }
    }
}

// ---------------------------------------------------------------------------
// K2: pair MLP — grid 32 (8 batches x 4 i-tiles), NOW 512 threads (16 warps:
// 4/SMSP latency hiding). Phase A: warp w computes B rows {2w, 2w+1} sharing
// each w_bot LDS; warps 0..7 additionally compute one A row each.
// Phase B unchanged on threads 0..255.
// ---------------------------------------------------------------------------
__global__ __launch_bounds__(512) void pair_mlp_kernel(
    const float* __restrict__ vec, const float* __restrict__ W1,
    const float* __restrict__ b1, const float* __restrict__ W2,
    const float* __restrict__ b2, float* __restrict__ conn)
{
    const int b    = blockIdx.x >> 2;
    const int tile = blockIdx.x & 3;        // i in [tile*8, tile*8+8)
    const int t    = threadIdx.x;           // 0..511

    __shared__ float sW1[128 * 32];         // 16 KB
    __shared__ float sV[32][64];            // 8 KB
    __shared__ float sA[8][SEGS];
    __shared__ float sB[32][SEGS];
    __shared__ float sW2[128];
    __shared__ float sb1[32];
    __shared__ float sb2[4];

    {
        const float4* w4 = (const float4*)W1;       // 1024 float4
        ((float4*)sW1)[t]       = w4[t];
        ((float4*)sW1)[t + 512] = w4[t + 512];
        const float4* v4 = (const float4*)(vec + (size_t)b * 2048);  // 512 float4
        ((float4*)sV)[t] = v4[t];
        if (t < 128) sW2[t] = W2[t];
        if (t < 32)  sb1[t] = b1[t];
        if (t < 4)   sb2[t] = b2[t];
    }
    __syncthreads();

    // Phase A
    {
        const int w = t >> 5;               // warp 0..15 (warp-uniform)
        const int k = t & 31;               // lane
        const int j0 = w * 2;               // B rows j0, j0+1
        const int j1 = j0 + 1;
        float bb0 = 0.f, bb1 = 0.f;
#pragma unroll 8
        for (int d = 0; d < 64; d++) {
            float wb = sW1[(64 + d) * 32 + k];      // conflict-free, shared by both j
            bb0 += sV[j0][d] * wb;                  // broadcast
            bb1 += sV[j1][d] * wb;
        }
        sB[j0][k] = bb0;
        sB[j1][k] = bb1;

        if (w < 8) {                         // A row i = tile*8 + w
            const int i = tile * 8 + w;
            float a = sb1[k];
#pragma unroll 8
            for (int d = 0; d < 64; d++)
                a += sV[i][d] * sW1[d * 32 + k];
            sA[w][k] = a;
        }
    }
    __syncthreads();

    // Phase B: 256 pairs on threads 0..255
    if (t < 256) {
        const int il = t >> 5;              // warp-uniform
        const int j  = t & 31;              // lane
        const int i  = tile * 8 + il;
        float o0 = sb2[0], o1 = sb2[1], o2 = sb2[2], o3 = sb2[3];
#pragma unroll
        for (int k = 0; k < 32; k++) {
            float h = sA[il][k] + sB[j][k];
            o0 += h * sW2[k * 4 + 0];
            o1 += h * sW2[k * 4 + 1];
            o2 += h * sW2[k * 4 + 2];
            o3 += h * sW2[k * 4 + 3];
        }
        float* cb = conn + (size_t)b * 4096 + j * 32 + i;
        cb[0]    = 1.f / (1.f + __expf(-o0));
        cb[1024] = 1.f / (1.f + __expf(-o1));
        cb[2048] = 1.f / (1.f + __expf(-o2));
        cb[3072] = 1.f / (1.f + __expf(-o3));
    }
}

// ---------------------------------------------------------------------------
extern "C" void kernel_launch(void* const* d_in, const int* in_sizes, int n_in,
                              void* d_out, int out_size)
{
    const float* enc   = (const float*)d_in[0];
    const int*   masks = (const int*)  d_in[1];
    const float* W1    = (const float*)d_in[2];
    const float* b1    = (const float*)d_in[3];
    const float* W2    = (const float*)d_in[4];
    const float* b2    = (const float*)d_in[5];

    float* out_f = (float*)d_out;
    float* vectors = out_f;
    float* conn    = out_f + BATCH * NOBJ * FDIM;

    static bool attr_done = false;
    if (!attr_done) {
        cudaFuncSetAttribute(segmax_kernel,
                             cudaFuncAttributeMaxDynamicSharedMemorySize,
                             SEGS * 256 * (int)sizeof(float2));
        attr_done = true;
    }

    pack_mask_kernel<<<512, 256>>>(masks);
    segmax_kernel<<<BATCH * 32, 256, SEGS * 256 * sizeof(float2)>>>(enc, vectors);
    pair_mlp_kernel<<<BATCH * 4, 512>>>(vectors, W1, b1, W2, b2, conn);
}